// round 10
// baseline (speedup 1.0000x reference)
#include <cuda_runtime.h>
#include <cuda_fp16.h>
#include <cuda_bf16.h>
#include <cstdint>

#define M_TOT 256
#define N_TOT 16384
#define K_TOT 4096
#define GPR   (K_TOT / 16)           // 256 groups per row

#define M_TILE 128
#define N_TILE 128
#define K_CHUNK 64
#define NCHUNK (K_TOT / K_CHUNK)     // 64
#define NSTAGE 3
#define THREADS 384                  // 8 consumer warps + 4 producer warps
#define NCONS 256                    // consumer threads
#define K_PAD 72                     // halves per row; 144B stride

#define A_BYTES (M_TILE * K_PAD * 2)    // 18432
#define B_BYTES (N_TILE * K_PAD * 2)    // 18432
#define STAGE_BYTES (A_BYTES + B_BYTES) // 36864
#define SMEM_BYTES (STAGE_BYTES * NSTAGE) // 110592

#define NB_X 512

// ---------------- device scratch ----------------
__device__ __half g_xh[M_TOT * K_TOT]; // x in fp16 (2 MB)
__device__ int    g_norm_dtype;        // 0=fp16, 1=bf16, 2=fp32

__device__ __forceinline__ uint32_t smem_u32(const void* p) {
    uint32_t a;
    asm("{ .reg .u64 t; cvta.to.shared.u64 t, %1; cvt.u32.u64 %0, t; }" : "=r"(a) : "l"(p));
    return a;
}
#define CP_ASYNC16(dst, src) \
    asm volatile("cp.async.cg.shared.global [%0], [%1], 16;" :: "r"(dst), "l"(src) : "memory")
#define CP_COMMIT() asm volatile("cp.async.commit_group;" ::: "memory")
#define CP_WAIT0()  asm volatile("cp.async.wait_group 0;" ::: "memory")
#define LDSM_X4(r0, r1, r2, r3, a) \
    asm volatile("ldmatrix.sync.aligned.m8n8.x4.shared.b16 {%0,%1,%2,%3}, [%4];" \
        : "=r"(r0), "=r"(r1), "=r"(r2), "=r"(r3) : "r"(a))
#define MMAF32(acc, a0, a1, a2, a3, b0, b1)                                    \
    asm volatile("mma.sync.aligned.m16n8k16.row.col.f32.f16.f16.f32 "          \
        "{%0,%1,%2,%3}, {%4,%5,%6,%7}, {%8,%9}, {%0,%1,%2,%3};\n"              \
        : "+f"((acc)[0]), "+f"((acc)[1]), "+f"((acc)[2]), "+f"((acc)[3])       \
        : "r"(a0), "r"(a1), "r"(a2), "r"(a3), "r"(b0), "r"(b1))
// named barriers: ids 1..3 = FULL[s], 4..6 = EMPTY[s]; count always 384
#define BAR_SYNC(id)   asm volatile("bar.sync %0, %1;"   :: "r"(id), "n"(THREADS) : "memory")
#define BAR_ARRIVE(id) asm volatile("bar.arrive %0, %1;" :: "r"(id), "n"(THREADS) : "memory")

// ---------------- prepass: x fp32->fp16 + norm dtype detect ----------------
__global__ void prepass(const uint16_t* __restrict__ pnorm,
                        const float* __restrict__ x)
{
    const int tid = threadIdx.x;
    const int b = blockIdx.x;

    if (b == 0 && tid < 32) {
        bool okh = true, okb = true, bigh = false, bigb = false;
#pragma unroll
        for (int i = 0; i < 8; i++) {
            uint16_t r = pnorm[tid * 8 + i];
            float vh = __half2float(*(const __half*)&r);
            float vb = __bfloat162float(*(const __nv_bfloat16*)&r);
            okh &= (vh > 1e-6f && vh < 1.0f);
            okb &= (vb > 1e-6f && vb < 1.0f);
            bigh |= (vh > 0.1f);
            bigb |= (vb > 0.1f);
        }
        bool allh = __all_sync(0xffffffffu, okh);
        bool allb = __all_sync(0xffffffffu, okb);
        bool anyh = __any_sync(0xffffffffu, bigh);
        bool anyb = __any_sync(0xffffffffu, bigb);
        if (tid == 0)
            g_norm_dtype = (allh && anyh) ? 0 : ((allb && anyb) ? 1 : 2);
    }

    const int base = (b * 256 + tid) * 8;
    float4 v0 = *(const float4*)(x + base);
    float4 v1 = *(const float4*)(x + base + 4);
    __half2 o[4];
    o[0] = __floats2half2_rn(v0.x, v0.y);
    o[1] = __floats2half2_rn(v0.z, v0.w);
    o[2] = __floats2half2_rn(v1.x, v1.y);
    o[3] = __floats2half2_rn(v1.z, v1.w);
    *(uint4*)(g_xh + base) = *(uint4*)o;
}

// dequant one group's 4 packed words into 8 half2 words; nf = norm in fp32
__device__ __forceinline__ void dequant_group(const int4 q, float nf,
                                              uint32_t hv[8])
{
    const uint32_t MAGIC = 0x64006400u;
    const __half2  magic_h2 = *(const __half2*)&MAGIC;
    __half2 tc2 = __half2half2(__float2half_rn(nf * (2.0f / 3.0f)));
    __half2 m32 = __half2half2(__float2half_rn(-nf));
    int words[4] = {q.x, q.y, q.z, q.w};
#pragma unroll
    for (int w = 0; w < 4; w++) {
        uint32_t qq = (uint32_t)words[w];
        uint32_t u01 = MAGIC | (qq & 3u) | ((qq & 0xCu) << 14);
        uint32_t u23 = MAGIC | ((qq >> 4) & 3u) | ((qq & 0xC0u) << 10);
        __half2 v01 = __hsub2(*(__half2*)&u01, magic_h2);
        __half2 v23 = __hsub2(*(__half2*)&u23, magic_h2);
        __half2 w01 = __hfma2(v01, tc2, m32);
        __half2 w23 = __hfma2(v23, tc2, m32);
        hv[w * 2]     = *(uint32_t*)&w01;
        hv[w * 2 + 1] = *(uint32_t*)&w23;
    }
}

// ---------------- main GEMM: warp-specialized producer/consumer ----------------
__global__ __launch_bounds__(THREADS)
void l2b_hmma(const int4* __restrict__ wq,
              const uint16_t* __restrict__ pnorm,
              const __half* __restrict__ xh,
              const float* __restrict__ bias,
              float* __restrict__ out)
{
    extern __shared__ char smem[];
    const uint32_t sb = smem_u32(smem);
    const int tid  = threadIdx.x;
    const int lane = tid & 31;
    const int warp = tid >> 5;
    const int noff = blockIdx.x * N_TILE;
    const int moff = blockIdx.y * M_TILE;

    if (warp < 8) {
        // ================= CONSUMER =================
        const int warp_m = warp >> 2;     // 0..1 : 64 M rows
        const int warp_n = warp & 3;      // 0..3 : 32 N cols
        float acc[2][8][4];
#pragma unroll
        for (int i = 0; i < 2; i++)
#pragma unroll
            for (int j = 0; j < 8; j++)
#pragma unroll
                for (int r = 0; r < 4; r++) acc[i][j][r] = 0.f;

        uint32_t aoff[2];
#pragma unroll
        for (int mi = 0; mi < 2; mi++)
            aoff[mi] = (uint32_t)(warp_m * 64 + (warp_n & 1) * 32 + mi * 16 + (lane & 15)) * (K_PAD * 2)
                     + ((lane >> 4) & 1) * 16;
        // NOTE: warp tile = 32M x 64N. M rows: warp_m*64 + (warp_n&1)*32 .. +32
        // N cols: (warp_n>>1)*64 .. +64  -> 2x2x(2x4) arrangement? No — keep R7 map:
        // R7 proven: warp covers rows [warp*32, warp*32+32) with warp = warp_m*... rebuild:
        // Use flat: warp w covers M rows [(w>>2)*64 + ... ] — revert to the R7-verified map below.
        const int wm = warp >> 2;         // 0..1
        const int wn = warp & 3;          // 0..3
#pragma unroll
        for (int mi = 0; mi < 2; mi++)
            aoff[mi] = (uint32_t)(wm * 64 + mi * 16 + (lane & 15)) * (K_PAD * 2)
                     + ((lane >> 4) & 1) * 16;
        // R7 map had warp tile 64M? No: R7 warp covered 32M (mi<2 over 32 rows: wm*32).
        // Here 8 warps cover 128M x 128N as 2x4: wm in {0,1} -> 64 rows each? That
        // needs mi<4. Keep EXACT R5/R9-style: wm2 = warp>>2 (0..1) covers 64 rows via
        // 2 frags of 16 + stride 32? NO. Final decision: 2x4 grid, warp tile 64Mx32N:
        // mi<4 frags. Rewrite cleanly:
        uint32_t aoff4[4];
#pragma unroll
        for (int mi = 0; mi < 4; mi++)
            aoff4[mi] = (uint32_t)(wm * 64 + mi * 16 + (lane & 15)) * (K_PAD * 2)
                      + ((lane >> 4) & 1) * 16;
        uint32_t boff[2];
#pragma unroll
        for (int np = 0; np < 2; np++)
            boff[np] = (uint32_t)(wn * 32 + np * 16 + ((lane & 7) | ((lane & 16) >> 1))) * (K_PAD * 2)
                     + ((lane >> 3) & 1) * 16;
        // acc shape: [4 mi][4 ni][4]
        float acc4[4][4][4];
#pragma unroll
        for (int i = 0; i < 4; i++)
#pragma unroll
            for (int j = 0; j < 4; j++)
#pragma unroll
                for (int r = 0; r < 4; r++) acc4[i][j][r] = 0.f;

        for (int c = 0; c < NCHUNK; ++c) {
            const int s = c % NSTAGE;
            const uint32_t abase = sb + s * STAGE_BYTES;
            const uint32_t bbase = abase + A_BYTES;
            BAR_SYNC(1 + s);   // wait FULL[s]
#pragma unroll
            for (int ks = 0; ks < 4; ++ks) {
                const uint32_t kb = ks * 32;
                uint32_t af[4][4];
#pragma unroll
                for (int mi = 0; mi < 4; mi++)
                    LDSM_X4(af[mi][0], af[mi][1], af[mi][2], af[mi][3],
                            abase + aoff4[mi] + kb);
#pragma unroll
                for (int np = 0; np < 2; np++) {
                    uint32_t b0, b1, b2, b3;
                    LDSM_X4(b0, b1, b2, b3, bbase + boff[np] + kb);
#pragma unroll
                    for (int e = 0; e < 2; e++) {
                        int ni = np * 2 + e;
                        uint32_t bb0 = e ? b2 : b0;
                        uint32_t bb1 = e ? b3 : b1;
#pragma unroll
                        for (int mi = 0; mi < 4; mi++)
                            MMAF32(acc4[mi][ni], af[mi][0], af[mi][1], af[mi][2], af[mi][3],
                                   bb0, bb1);
                    }
                }
            }
            BAR_ARRIVE(4 + s); // signal EMPTY[s]
        }

        // epilogue
#pragma unroll
        for (int mi = 0; mi < 4; mi++) {
            int r = moff + wm * 64 + mi * 16 + (lane >> 2);
#pragma unroll
            for (int ni = 0; ni < 4; ni++) {
                int ncol = noff + wn * 32 + ni * 8 + (lane & 3) * 2;
                float b0 = bias[ncol];
                float b1 = bias[ncol + 1];
                float2* o0 = (float2*)(out + (size_t)r * N_TOT + ncol);
                float2* o1 = (float2*)(out + (size_t)(r + 8) * N_TOT + ncol);
                *o0 = make_float2(acc4[mi][ni][0] + b0, acc4[mi][ni][1] + b1);
                *o1 = make_float2(acc4[mi][ni][2] + b0, acc4[mi][ni][3] + b1);
            }
        }
        (void)acc; (void)aoff;
    } else {
        // ================= PRODUCER =================
        const int ptid = tid - NCONS;     // 0..127
        const int dt = g_norm_dtype;
        int4     qr[4];
        uint32_t nr[4];

        auto loadW = [&](int c) {
#pragma unroll
            for (int h = 0; h < 4; h++) {
                int gl  = ptid + h * 128;
                int wn_ = gl >> 2;
                int wgi = gl & 3;
                int g   = (noff + wn_) * GPR + c * 4 + wgi;
                qr[h] = wq[g];
                if (dt == 2) nr[h] = ((const uint32_t*)pnorm)[g];
                else         nr[h] = pnorm[g];
            }
        };
        auto rawToF = [&](uint32_t r) -> float {
            if (dt == 0)      return __half2float(__ushort_as_half((unsigned short)r));
            else if (dt == 1) return __uint_as_float(r << 16);
            else              return __uint_as_float(r);
        };

        loadW(0);
        for (int c = 0; c < NCHUNK; ++c) {
            const int s = c % NSTAGE;
            const uint32_t abase = sb + s * STAGE_BYTES;
            const uint32_t bbase = abase + A_BYTES;
            if (c >= NSTAGE) BAR_SYNC(4 + s);   // wait EMPTY[s]

            // A: 1024 16B segs, 8 per producer thread
#pragma unroll
            for (int h = 0; h < 8; h++) {
                int seg = ptid + h * 128;
                int row = seg >> 3;
                int sg  = seg & 7;
                const __half* src = xh + (size_t)(moff + row) * K_TOT + c * K_CHUNK + sg * 8;
                uint32_t dst = abase + row * (K_PAD * 2) + sg * 16;
                CP_ASYNC16(dst, src);
            }
            CP_COMMIT();

            // B: dequant 4 groups (weights prefetched last iteration)
#pragma unroll
            for (int h = 0; h < 4; h++) {
                int gl  = ptid + h * 128;
                int wn_ = gl >> 2;
                int wgi = gl & 3;
                uint32_t hv[8];
                dequant_group(qr[h], rawToF(nr[h]), hv);
                uint32_t a0 = bbase + (uint32_t)wn_ * (K_PAD * 2) + wgi * 32;
                asm volatile("st.shared.v4.b32 [%0], {%1,%2,%3,%4};"
                    :: "r"(a0), "r"(hv[0]), "r"(hv[1]), "r"(hv[2]), "r"(hv[3]) : "memory");
                asm volatile("st.shared.v4.b32 [%0], {%1,%2,%3,%4};"
                    :: "r"(a0 + 16), "r"(hv[4]), "r"(hv[5]), "r"(hv[6]), "r"(hv[7]) : "memory");
            }

            // prefetch next chunk's weights while cp.async drains
            if (c + 1 < NCHUNK) loadW(c + 1);

            CP_WAIT0();
            BAR_ARRIVE(1 + s);   // signal FULL[s]
        }
    }
}

// ---------------- launcher ----------------
extern "C" void kernel_launch(void* const* d_in, const int* in_sizes, int n_in,
                              void* d_out, int out_size)
{
    // Bind by size order: wq > norm > x > bias
    int order[4] = {0, 1, 2, 3};
    for (int i = 1; i < 4 && i < n_in; i++) {
        int v = order[i], j = i - 1;
        while (j >= 0 && (long long)in_sizes[order[j]] < (long long)in_sizes[v]) {
            order[j + 1] = order[j]; j--;
        }
        order[j + 1] = v;
    }
    const int4*     wq    = (const int4*)d_in[order[0]];
    const uint16_t* pnorm = (const uint16_t*)d_in[order[1]];
    const float*    x     = (const float*)d_in[order[2]];
    const float*    bias  = (const float*)d_in[order[3]];
    float* out = (float*)d_out;

    prepass<<<NB_X, 256>>>(pnorm, x);

    __half* xh_dev = nullptr;
    cudaGetSymbolAddress((void**)&xh_dev, g_xh);

    cudaFuncSetAttribute(l2b_hmma, cudaFuncAttributeMaxDynamicSharedMemorySize, SMEM_BYTES);
    dim3 grid(N_TOT / N_TILE, M_TOT / M_TILE);   // (128, 2) = 256 CTAs
    l2b_hmma<<<grid, THREADS, SMEM_BYTES>>>(wq, pnorm, xh_dev, bias, out);
}

// round 11
// speedup vs baseline: 1.0950x; 1.0950x over previous
#include <cuda_runtime.h>
#include <cuda_fp16.h>
#include <cuda_bf16.h>
#include <cstdint>

#define M_TOT 256
#define N_TOT 16384
#define K_TOT 4096
#define GPR   (K_TOT / 16)           // 256 groups per row
#define NSTRIPS_TOT 1024             // N strips of 16
#define NCTAS 148

#define K_CHUNK 64
#define NCHUNK (K_TOT / K_CHUNK)     // 64
#define THREADS 256
#define K_PAD 72                     // halves per row; 144B stride
#define MAXSTRIP 7                   // max strips per CTA (112 N cols)

#define A_BYTES (M_TOT * K_PAD * 2)          // 36864
#define B_BYTES (MAXSTRIP * 16 * K_PAD * 2)  // 16128
#define SM_A0 0
#define SM_A1 (SM_A0 + A_BYTES)
#define SM_B0 (SM_A1 + A_BYTES)
#define SM_B1 (SM_B0 + B_BYTES)
#define SMEM_BYTES (SM_B1 + B_BYTES)         // 105984

#define NB_X 512

// ---------------- device scratch ----------------
__device__ __half g_xh[M_TOT * K_TOT]; // x in fp16 (2 MB)
__device__ int    g_norm_dtype;        // 0=fp16, 1=bf16, 2=fp32

__device__ __forceinline__ uint32_t smem_u32(const void* p) {
    uint32_t a;
    asm("{ .reg .u64 t; cvta.to.shared.u64 t, %1; cvt.u32.u64 %0, t; }" : "=r"(a) : "l"(p));
    return a;
}
#define CP_ASYNC16(dst, src) \
    asm volatile("cp.async.cg.shared.global [%0], [%1], 16;" :: "r"(dst), "l"(src) : "memory")
#define CP_COMMIT() asm volatile("cp.async.commit_group;" ::: "memory")
#define CP_WAIT0()  asm volatile("cp.async.wait_group 0;" ::: "memory")
#define LDSM_X4(r0, r1, r2, r3, a) \
    asm volatile("ldmatrix.sync.aligned.m8n8.x4.shared.b16 {%0,%1,%2,%3}, [%4];" \
        : "=r"(r0), "=r"(r1), "=r"(r2), "=r"(r3) : "r"(a))
#define MMAF32(acc, a0, a1, a2, a3, b0, b1)                                    \
    asm volatile("mma.sync.aligned.m16n8k16.row.col.f32.f16.f16.f32 "          \
        "{%0,%1,%2,%3}, {%4,%5,%6,%7}, {%8,%9}, {%0,%1,%2,%3};\n"              \
        : "+f"((acc)[0]), "+f"((acc)[1]), "+f"((acc)[2]), "+f"((acc)[3])       \
        : "r"(a0), "r"(a1), "r"(a2), "r"(a3), "r"(b0), "r"(b1))

// ---------------- prepass: x fp32->fp16 + norm dtype detect ----------------
__global__ void prepass(const uint16_t* __restrict__ pnorm,
                        const float* __restrict__ x)
{
    const int tid = threadIdx.x;
    const int b = blockIdx.x;

    if (b == 0 && tid < 32) {
        bool okh = true, okb = true, bigh = false, bigb = false;
#pragma unroll
        for (int i = 0; i < 8; i++) {
            uint16_t r = pnorm[tid * 8 + i];
            float vh = __half2float(*(const __half*)&r);
            float vb = __bfloat162float(*(const __nv_bfloat16*)&r);
            okh &= (vh > 1e-6f && vh < 1.0f);
            okb &= (vb > 1e-6f && vb < 1.0f);
            bigh |= (vh > 0.1f);
            bigb |= (vb > 0.1f);
        }
        bool allh = __all_sync(0xffffffffu, okh);
        bool allb = __all_sync(0xffffffffu, okb);
        bool anyh = __any_sync(0xffffffffu, bigh);
        bool anyb = __any_sync(0xffffffffu, bigb);
        if (tid == 0)
            g_norm_dtype = (allh && anyh) ? 0 : ((allb && anyb) ? 1 : 2);
    }

    const int base = (b * 256 + tid) * 8;
    float4 v0 = *(const float4*)(x + base);
    float4 v1 = *(const float4*)(x + base + 4);
    __half2 o[4];
    o[0] = __floats2half2_rn(v0.x, v0.y);
    o[1] = __floats2half2_rn(v0.z, v0.w);
    o[2] = __floats2half2_rn(v1.x, v1.y);
    o[3] = __floats2half2_rn(v1.z, v1.w);
    *(uint4*)(g_xh + base) = *(uint4*)o;
}

// dequant one group's 4 packed words into 8 half2 words; nf = norm in fp32
__device__ __forceinline__ void dequant_group(const int4 q, float nf,
                                              uint32_t hv[8])
{
    const uint32_t MAGIC = 0x64006400u;
    const __half2  magic_h2 = *(const __half2*)&MAGIC;
    __half2 tc2 = __half2half2(__float2half_rn(nf * (2.0f / 3.0f)));
    __half2 m32 = __half2half2(__float2half_rn(-nf));
    int words[4] = {q.x, q.y, q.z, q.w};
#pragma unroll
    for (int w = 0; w < 4; w++) {
        uint32_t qq = (uint32_t)words[w];
        uint32_t u01 = MAGIC | (qq & 3u) | ((qq & 0xCu) << 14);
        uint32_t u23 = MAGIC | ((qq >> 4) & 3u) | ((qq & 0xC0u) << 10);
        __half2 v01 = __hsub2(*(__half2*)&u01, magic_h2);
        __half2 v23 = __hsub2(*(__half2*)&u23, magic_h2);
        __half2 w01 = __hfma2(v01, tc2, m32);
        __half2 w23 = __hfma2(v23, tc2, m32);
        hv[w * 2]     = *(uint32_t*)&w01;
        hv[w * 2 + 1] = *(uint32_t*)&w23;
    }
}

// ---------------- main GEMM: 148 CTAs, full-M, 6-7 N-strips each ----------------
__global__ __launch_bounds__(THREADS, 1)
void l2b_hmma(const int4* __restrict__ wq,
              const uint16_t* __restrict__ pnorm,
              const __half* __restrict__ xh,
              const float* __restrict__ bias,
              float* __restrict__ out)
{
    extern __shared__ char smem[];
    const uint32_t sb = smem_u32(smem);
    const int tid  = threadIdx.x;
    const int lane = tid & 31;
    const int warp = tid >> 5;        // 0..7 : 32 M rows each, all N strips
    const int bid  = blockIdx.x;

    // strip share: [s0, s1) of 1024 strips
    const int s0 = (bid * NSTRIPS_TOT) / NCTAS;
    const int s1 = ((bid + 1) * NSTRIPS_TOT) / NCTAS;
    const int nstrips = s1 - s0;       // 6 or 7
    const int nbase = s0 * 16;         // first N column
    const int ngroups = nstrips * 64;  // B groups per chunk (<= 448)
    const int dt = g_norm_dtype;

    // acc[mi][si][e][4] : 32M x (nstrips*16)N
    float acc[2][MAXSTRIP][2][4];
#pragma unroll
    for (int mi = 0; mi < 2; mi++)
#pragma unroll
        for (int si = 0; si < MAXSTRIP; si++)
#pragma unroll
            for (int e = 0; e < 2; e++)
#pragma unroll
                for (int r = 0; r < 4; r++) acc[mi][si][e][r] = 0.f;

    int4     qr[2];
    uint32_t nr[2];
    const bool has1 = (tid + 256) < ngroups;   // ngroups in [384, 448]

    // A staging: 2048 16B segs, 8 per thread
    auto issueA = [&](int c, uint32_t abase) {
#pragma unroll
        for (int h = 0; h < 8; h++) {
            int seg = tid + h * 256;
            int row = seg >> 3;
            int s   = seg & 7;
            const __half* src = xh + (size_t)row * K_TOT + c * K_CHUNK + s * 8;
            uint32_t dst = abase + row * (K_PAD * 2) + s * 16;
            CP_ASYNC16(dst, src);
        }
        CP_COMMIT();
    };
    // B staging: up to 448 groups, 2 per thread (second predicated)
    auto loadW = [&](int c) {
        {
            int wn  = tid >> 2;
            int wgi = tid & 3;
            int g   = (nbase + wn) * GPR + c * 4 + wgi;
            qr[0] = wq[g];
            if (dt == 2) nr[0] = ((const uint32_t*)pnorm)[g];
            else         nr[0] = pnorm[g];
        }
        if (has1) {
            int gl  = tid + 256;
            int wn  = gl >> 2;
            int wgi = gl & 3;
            int g   = (nbase + wn) * GPR + c * 4 + wgi;
            qr[1] = wq[g];
            if (dt == 2) nr[1] = ((const uint32_t*)pnorm)[g];
            else         nr[1] = pnorm[g];
        }
    };
    auto rawToF = [&](uint32_t r) -> float {
        if (dt == 0)      return __half2float(__ushort_as_half((unsigned short)r));
        else if (dt == 1) return __uint_as_float(r << 16);
        else              return __uint_as_float(r);
    };

    issueA(0, sb + SM_A0);
    loadW(0);

    uint32_t aoff[2];
#pragma unroll
    for (int mi = 0; mi < 2; mi++)
        aoff[mi] = (uint32_t)(warp * 32 + mi * 16 + (lane & 15)) * (K_PAD * 2)
                 + ((lane >> 4) & 1) * 16;
    const uint32_t blane = (uint32_t)((lane & 7) | ((lane & 16) >> 1)) * (K_PAD * 2)
                         + ((lane >> 3) & 1) * 16;

    const uint32_t st0 = (uint32_t)(tid >> 2) * (K_PAD * 2) + (tid & 3) * 32;
    const uint32_t st1 = (uint32_t)((tid + 256) >> 2) * (K_PAD * 2) + (tid & 3) * 32;

    for (int c = 0; c < NCHUNK; ++c) {
        const int pb = c & 1;
        const uint32_t abase = sb + (pb ? SM_A1 : SM_A0);
        const uint32_t bbase = sb + (pb ? SM_B1 : SM_B0);

        // ---- dequant + STS B(c)
        {
            uint32_t hv[8];
            dequant_group(qr[0], rawToF(nr[0]), hv);
            asm volatile("st.shared.v4.b32 [%0], {%1,%2,%3,%4};"
                :: "r"(bbase + st0), "r"(hv[0]), "r"(hv[1]), "r"(hv[2]), "r"(hv[3]) : "memory");
            asm volatile("st.shared.v4.b32 [%0], {%1,%2,%3,%4};"
                :: "r"(bbase + st0 + 16), "r"(hv[4]), "r"(hv[5]), "r"(hv[6]), "r"(hv[7]) : "memory");
            if (has1) {
                dequant_group(qr[1], rawToF(nr[1]), hv);
                asm volatile("st.shared.v4.b32 [%0], {%1,%2,%3,%4};"
                    :: "r"(bbase + st1), "r"(hv[0]), "r"(hv[1]), "r"(hv[2]), "r"(hv[3]) : "memory");
                asm volatile("st.shared.v4.b32 [%0], {%1,%2,%3,%4};"
                    :: "r"(bbase + st1 + 16), "r"(hv[4]), "r"(hv[5]), "r"(hv[6]), "r"(hv[7]) : "memory");
            }
        }

        CP_WAIT0();
        __syncthreads();

        if (c + 1 < NCHUNK) {
            issueA(c + 1, sb + (pb ? SM_A0 : SM_A1));
            loadW(c + 1);
        }

        // ---- compute chunk c
#pragma unroll
        for (int ks = 0; ks < 4; ++ks) {
            const uint32_t kb = ks * 32;
            uint32_t a0, a1, a2, a3, a4, a5, a6, a7;
            LDSM_X4(a0, a1, a2, a3, abase + aoff[0] + kb);
            LDSM_X4(a4, a5, a6, a7, abase + aoff[1] + kb);
#pragma unroll
            for (int si = 0; si < MAXSTRIP; si++) {
                if (si < nstrips) {
                    uint32_t b0, b1, b2, b3;
                    LDSM_X4(b0, b1, b2, b3, bbase + (uint32_t)si * (16 * K_PAD * 2) + blane + kb);
#pragma unroll
                    for (int e = 0; e < 2; e++) {
                        uint32_t bb0 = e ? b2 : b0;
                        uint32_t bb1 = e ? b3 : b1;
                        MMAF32(acc[0][si][e], a0, a1, a2, a3, bb0, bb1);
                        MMAF32(acc[1][si][e], a4, a5, a6, a7, bb0, bb1);
                    }
                }
            }
        }
    }

    // ---- epilogue: bias + fp32 store
#pragma unroll
    for (int mi = 0; mi < 2; mi++) {
        int r = warp * 32 + mi * 16 + (lane >> 2);
#pragma unroll
        for (int si = 0; si < MAXSTRIP; si++) {
            if (si < nstrips) {
#pragma unroll
                for (int e = 0; e < 2; e++) {
                    int ncol = nbase + si * 16 + e * 8 + (lane & 3) * 2;
                    float b0 = bias[ncol];
                    float b1 = bias[ncol + 1];
                    float2* o0 = (float2*)(out + (size_t)r * N_TOT + ncol);
                    float2* o1 = (float2*)(out + (size_t)(r + 8) * N_TOT + ncol);
                    *o0 = make_float2(acc[mi][si][e][0] + b0, acc[mi][si][e][1] + b1);
                    *o1 = make_float2(acc[mi][si][e][2] + b0, acc[mi][si][e][3] + b1);
                }
            }
        }
    }
}

// ---------------- launcher ----------------
extern "C" void kernel_launch(void* const* d_in, const int* in_sizes, int n_in,
                              void* d_out, int out_size)
{
    // Bind by size order: wq > norm > x > bias
    int order[4] = {0, 1, 2, 3};
    for (int i = 1; i < 4 && i < n_in; i++) {
        int v = order[i], j = i - 1;
        while (j >= 0 && (long long)in_sizes[order[j]] < (long long)in_sizes[v]) {
            order[j + 1] = order[j]; j--;
        }
        order[j + 1] = v;
    }
    const int4*     wq    = (const int4*)d_in[order[0]];
    const uint16_t* pnorm = (const uint16_t*)d_in[order[1]];
    const float*    x     = (const float*)d_in[order[2]];
    const float*    bias  = (const float*)d_in[order[3]];
    float* out = (float*)d_out;

    prepass<<<NB_X, 256>>>(pnorm, x);

    __half* xh_dev = nullptr;
    cudaGetSymbolAddress((void**)&xh_dev, g_xh);

    cudaFuncSetAttribute(l2b_hmma, cudaFuncAttributeMaxDynamicSharedMemorySize, SMEM_BYTES);
    l2b_hmma<<<NCTAS, THREADS, SMEM_BYTES>>>(wq, pnorm, xh_dev, bias, out);
}

// round 12
// speedup vs baseline: 1.2276x; 1.1211x over previous
#include <cuda_runtime.h>
#include <cuda_fp16.h>
#include <cuda_bf16.h>
#include <cstdint>

#define M_TOT 256
#define N_TOT 16384
#define K_TOT 4096
#define G_TOT (N_TOT * K_TOT / 16)
#define GPR   (K_TOT / 16)           // 256 groups per row
#define NCTAS 148
#define NSTRIP 7                     // compile-time strips/CTA (16 N cols each)

#define K_CHUNK 64
#define NCHUNK (K_TOT / K_CHUNK)     // 64
#define THREADS 256
#define ROW_B 128                    // bytes per row: 64 halves, XOR-swizzled

#define A_BYTES (M_TOT * ROW_B)              // 32768
#define B_BYTES (NSTRIP * 16 * ROW_B)        // 14336
#define SM_A0 0
#define SM_A1 (SM_A0 + A_BYTES)
#define SM_B0 (SM_A1 + A_BYTES)
#define SM_B1 (SM_B0 + B_BYTES)
#define SMEM_BYTES (SM_B1 + B_BYTES)         // 94208

#define NB_X 512

// ---------------- device scratch ----------------
__device__ __half g_xh[M_TOT * K_TOT]; // x in fp16 (2 MB)
__device__ int    g_norm_dtype;        // 0=fp16, 1=bf16, 2=fp32

__device__ __forceinline__ uint32_t smem_u32(const void* p) {
    uint32_t a;
    asm("{ .reg .u64 t; cvta.to.shared.u64 t, %1; cvt.u32.u64 %0, t; }" : "=r"(a) : "l"(p));
    return a;
}
#define CP_ASYNC16(dst, src) \
    asm volatile("cp.async.cg.shared.global [%0], [%1], 16;" :: "r"(dst), "l"(src) : "memory")
#define CP_COMMIT() asm volatile("cp.async.commit_group;" ::: "memory")
#define CP_WAIT0()  asm volatile("cp.async.wait_group 0;" ::: "memory")
#define LDSM_X4(r0, r1, r2, r3, a) \
    asm volatile("ldmatrix.sync.aligned.m8n8.x4.shared.b16 {%0,%1,%2,%3}, [%4];" \
        : "=r"(r0), "=r"(r1), "=r"(r2), "=r"(r3) : "r"(a))
#define MMAF32(acc, a0, a1, a2, a3, b0, b1)                                    \
    asm volatile("mma.sync.aligned.m16n8k16.row.col.f32.f16.f16.f32 "          \
        "{%0,%1,%2,%3}, {%4,%5,%6,%7}, {%8,%9}, {%0,%1,%2,%3};\n"              \
        : "+f"((acc)[0]), "+f"((acc)[1]), "+f"((acc)[2]), "+f"((acc)[3])       \
        : "r"(a0), "r"(a1), "r"(a2), "r"(a3), "r"(b0), "r"(b1))

// ---------------- prepass: x fp32->fp16 + norm dtype detect ----------------
__global__ void prepass(const uint16_t* __restrict__ pnorm,
                        const float* __restrict__ x)
{
    const int tid = threadIdx.x;
    const int b = blockIdx.x;

    if (b == 0 && tid < 32) {
        bool okh = true, okb = true, bigh = false, bigb = false;
#pragma unroll
        for (int i = 0; i < 8; i++) {
            uint16_t r = pnorm[tid * 8 + i];
            float vh = __half2float(*(const __half*)&r);
            float vb = __bfloat162float(*(const __nv_bfloat16*)&r);
            okh &= (vh > 1e-6f && vh < 1.0f);
            okb &= (vb > 1e-6f && vb < 1.0f);
            bigh |= (vh > 0.1f);
            bigb |= (vb > 0.1f);
        }
        bool allh = __all_sync(0xffffffffu, okh);
        bool allb = __all_sync(0xffffffffu, okb);
        bool anyh = __any_sync(0xffffffffu, bigh);
        bool anyb = __any_sync(0xffffffffu, bigb);
        if (tid == 0)
            g_norm_dtype = (allh && anyh) ? 0 : ((allb && anyb) ? 1 : 2);
    }

    const int base = (b * 256 + tid) * 8;
    float4 v0 = *(const float4*)(x + base);
    float4 v1 = *(const float4*)(x + base + 4);
    __half2 o[4];
    o[0] = __floats2half2_rn(v0.x, v0.y);
    o[1] = __floats2half2_rn(v0.z, v0.w);
    o[2] = __floats2half2_rn(v1.x, v1.y);
    o[3] = __floats2half2_rn(v1.z, v1.w);
    *(uint4*)(g_xh + base) = *(uint4*)o;
}

// dequant one group's 4 packed words into 8 half2 words; nf = norm in fp32
__device__ __forceinline__ void dequant_group(const int4 q, float nf,
                                              uint32_t hv[8])
{
    const uint32_t MAGIC = 0x64006400u;
    const __half2  magic_h2 = *(const __half2*)&MAGIC;
    __half2 tc2 = __half2half2(__float2half_rn(nf * (2.0f / 3.0f)));
    __half2 m32 = __half2half2(__float2half_rn(-nf));
    int words[4] = {q.x, q.y, q.z, q.w};
#pragma unroll
    for (int w = 0; w < 4; w++) {
        uint32_t qq = (uint32_t)words[w];
        uint32_t u01 = MAGIC | (qq & 3u) | ((qq & 0xCu) << 14);
        uint32_t u23 = MAGIC | ((qq >> 4) & 3u) | ((qq & 0xC0u) << 10);
        __half2 v01 = __hsub2(*(__half2*)&u01, magic_h2);
        __half2 v23 = __hsub2(*(__half2*)&u23, magic_h2);
        __half2 w01 = __hfma2(v01, tc2, m32);
        __half2 w23 = __hfma2(v23, tc2, m32);
        hv[w * 2]     = *(uint32_t*)&w01;
        hv[w * 2 + 1] = *(uint32_t*)&w23;
    }
}

// ---------------- main GEMM: 148 CTAs, full-M, 7 strips, swizzled smem ----------------
__global__ __launch_bounds__(THREADS, 1)
void l2b_hmma(const int4* __restrict__ wq,
              const uint16_t* __restrict__ pnorm,
              const __half* __restrict__ xh,
              const float* __restrict__ bias,
              float* __restrict__ out)
{
    extern __shared__ char smem[];
    const uint32_t sb = smem_u32(smem);
    const int tid  = threadIdx.x;
    const int lane = tid & 31;
    const int warp = tid >> 5;        // 0..7 : 32 M rows each, all 7 strips
    const int bid  = blockIdx.x;

    const int nbase = bid * (NSTRIP * 16);      // first N column (may exceed N_TOT)
    const int dt = g_norm_dtype;

    float acc[2][NSTRIP][2][4];
#pragma unroll
    for (int mi = 0; mi < 2; mi++)
#pragma unroll
        for (int si = 0; si < NSTRIP; si++)
#pragma unroll
            for (int e = 0; e < 2; e++)
#pragma unroll
                for (int r = 0; r < 4; r++) acc[mi][si][e][r] = 0.f;

    int4     qr[2];
    uint32_t nr[2];
    const bool has1 = (tid + 256) < NSTRIP * 64;   // 448 groups; tid+256 < 448

    // A staging: 2048 16B segs, 8 per thread; swizzled dst
    auto issueA = [&](int c, uint32_t abase) {
#pragma unroll
        for (int h = 0; h < 8; h++) {
            int seg = tid + h * 256;
            int row = seg >> 3;
            int s   = seg & 7;
            const __half* src = xh + (size_t)row * K_TOT + c * K_CHUNK + s * 8;
            uint32_t dst = abase + row * ROW_B + ((s ^ (row & 7)) << 4);
            CP_ASYNC16(dst, src);
        }
        CP_COMMIT();
    };
    // B staging: 448 groups, 2 per thread (second predicated); clamped col
    auto loadW = [&](int c) {
        {
            int col = nbase + (tid >> 2);
            col = col < N_TOT ? col : N_TOT - 1;
            int g   = col * GPR + c * 4 + (tid & 3);
            qr[0] = wq[g];
            if (dt == 2) nr[0] = ((const uint32_t*)pnorm)[g];
            else         nr[0] = pnorm[g];
        }
        if (has1) {
            int col = nbase + ((tid + 256) >> 2);
            col = col < N_TOT ? col : N_TOT - 1;
            int g   = col * GPR + c * 4 + (tid & 3);
            qr[1] = wq[g];
            if (dt == 2) nr[1] = ((const uint32_t*)pnorm)[g];
            else         nr[1] = pnorm[g];
        }
    };
    auto rawToF = [&](uint32_t r) -> float {
        if (dt == 0)      return __half2float(__ushort_as_half((unsigned short)r));
        else if (dt == 1) return __uint_as_float(r << 16);
        else              return __uint_as_float(r);
    };

    issueA(0, sb + SM_A0);
    loadW(0);

    // LDSM addressing (swizzled): A rows r = warp*32 + mi*16 + (lane&15)
    uint32_t a_rb[2], a_x7[2];
#pragma unroll
    for (int mi = 0; mi < 2; mi++) {
        int r = warp * 32 + mi * 16 + (lane & 15);
        a_rb[mi] = (uint32_t)r * ROW_B;
        a_x7[mi] = (uint32_t)(r & 7);
    }
    const uint32_t a_wb = (lane >> 4) & 1;
    // B rows n = si*16 + ((lane&7)|((lane&16)>>1))
    const uint32_t b_nl = (uint32_t)((lane & 7) | ((lane & 16) >> 1));
    const uint32_t b_rb = b_nl * ROW_B;
    const uint32_t b_x7 = b_nl & 7;            // = lane & 7
    const uint32_t b_wb = (lane >> 3) & 1;

    // STS addressing: group0 (wn=tid>>2, wgi=tid&3), group1 (wn+64)
    const uint32_t g0_wn = tid >> 2, g0_wgi = tid & 3;
    const uint32_t g1_wn = g0_wn + 64;
    const uint32_t sts00 = g0_wn * ROW_B + (((2 * g0_wgi) ^ (g0_wn & 7)) << 4);
    const uint32_t sts01 = g0_wn * ROW_B + (((2 * g0_wgi + 1) ^ (g0_wn & 7)) << 4);
    const uint32_t sts10 = g1_wn * ROW_B + (((2 * g0_wgi) ^ (g1_wn & 7)) << 4);
    const uint32_t sts11 = g1_wn * ROW_B + (((2 * g0_wgi + 1) ^ (g1_wn & 7)) << 4);

    for (int c = 0; c < NCHUNK; ++c) {
        const int pb = c & 1;
        const uint32_t abase = sb + (pb ? SM_A1 : SM_A0);
        const uint32_t bbase = sb + (pb ? SM_B1 : SM_B0);

        // ---- dequant + STS B(c) (conflict-free swizzled)
        {
            uint32_t hv[8];
            dequant_group(qr[0], rawToF(nr[0]), hv);
            asm volatile("st.shared.v4.b32 [%0], {%1,%2,%3,%4};"
                :: "r"(bbase + sts00), "r"(hv[0]), "r"(hv[1]), "r"(hv[2]), "r"(hv[3]) : "memory");
            asm volatile("st.shared.v4.b32 [%0], {%1,%2,%3,%4};"
                :: "r"(bbase + sts01), "r"(hv[4]), "r"(hv[5]), "r"(hv[6]), "r"(hv[7]) : "memory");
            if (has1) {
                dequant_group(qr[1], rawToF(nr[1]), hv);
                asm volatile("st.shared.v4.b32 [%0], {%1,%2,%3,%4};"
                    :: "r"(bbase + sts10), "r"(hv[0]), "r"(hv[1]), "r"(hv[2]), "r"(hv[3]) : "memory");
                asm volatile("st.shared.v4.b32 [%0], {%1,%2,%3,%4};"
                    :: "r"(bbase + sts11), "r"(hv[4]), "r"(hv[5]), "r"(hv[6]), "r"(hv[7]) : "memory");
            }
        }

        CP_WAIT0();
        __syncthreads();

        if (c + 1 < NCHUNK) {
            issueA(c + 1, sb + (pb ? SM_A0 : SM_A1));
            loadW(c + 1);
        }

        // ---- compute chunk c
#pragma unroll
        for (int ks = 0; ks < 4; ++ks) {
            uint32_t a0, a1, a2, a3, a4, a5, a6, a7;
            {
                uint32_t w = ks * 2 + a_wb;
                LDSM_X4(a0, a1, a2, a3, abase + a_rb[0] + ((w ^ a_x7[0]) << 4));
                LDSM_X4(a4, a5, a6, a7, abase + a_rb[1] + ((w ^ a_x7[1]) << 4));
            }
#pragma unroll
            for (int si = 0; si < NSTRIP; si++) {
                uint32_t b0, b1, b2, b3;
                {
                    uint32_t w = ks * 2 + b_wb;
                    LDSM_X4(b0, b1, b2, b3,
                            bbase + (uint32_t)si * (16 * ROW_B) + b_rb + ((w ^ b_x7) << 4));
                }
#pragma unroll
                for (int e = 0; e < 2; e++) {
                    uint32_t bb0 = e ? b2 : b0;
                    uint32_t bb1 = e ? b3 : b1;
                    MMAF32(acc[0][si][e], a0, a1, a2, a3, bb0, bb1);
                    MMAF32(acc[1][si][e], a4, a5, a6, a7, bb0, bb1);
                }
            }
        }
    }

    // ---- epilogue: bias + fp32 store (guarded for padded N)
#pragma unroll
    for (int mi = 0; mi < 2; mi++) {
        int r = warp * 32 + mi * 16 + (lane >> 2);
#pragma unroll
        for (int si = 0; si < NSTRIP; si++) {
#pragma unroll
            for (int e = 0; e < 2; e++) {
                int ncol = nbase + si * 16 + e * 8 + (lane & 3) * 2;
                if (ncol < N_TOT) {
                    float b0 = bias[ncol];
                    float b1 = bias[ncol + 1];
                    float2* o0 = (float2*)(out + (size_t)r * N_TOT + ncol);
                    float2* o1 = (float2*)(out + (size_t)(r + 8) * N_TOT + ncol);
                    *o0 = make_float2(acc[mi][si][e][0] + b0, acc[mi][si][e][1] + b1);
                    *o1 = make_float2(acc[mi][si][e][2] + b0, acc[mi][si][e][3] + b1);
                }
            }
        }
    }
}

// ---------------- launcher ----------------
extern "C" void kernel_launch(void* const* d_in, const int* in_sizes, int n_in,
                              void* d_out, int out_size)
{
    // Bind by size order: wq > norm > x > bias
    int order[4] = {0, 1, 2, 3};
    for (int i = 1; i < 4 && i < n_in; i++) {
        int v = order[i], j = i - 1;
        while (j >= 0 && (long long)in_sizes[order[j]] < (long long)in_sizes[v]) {
            order[j + 1] = order[j]; j--;
        }
        order[j + 1] = v;
    }
    const int4*     wq    = (const int4*)d_in[order[0]];
    const uint16_t* pnorm = (const uint16_t*)d_in[order[1]];
    const float*    x     = (const float*)d_in[order[2]];
    const float*    bias  = (const float*)d_in[order[3]];
    float* out = (float*)d_out;

    prepass<<<NB_X, 256>>>(pnorm, x);

    __half* xh_dev = nullptr;
    cudaGetSymbolAddress((void**)&xh_dev, g_xh);

    cudaFuncSetAttribute(l2b_hmma, cudaFuncAttributeMaxDynamicSharedMemorySize, SMEM_BYTES);
    l2b_hmma<<<NCTAS, THREADS, SMEM_BYTES>>>(wq, pnorm, xh_dev, bias, out);
}

// round 13
// speedup vs baseline: 1.2554x; 1.0226x over previous
#include <cuda_runtime.h>
#include <cuda_fp16.h>
#include <cuda_bf16.h>
#include <cstdint>

#define M_TOT 256
#define N_TOT 16384
#define K_TOT 4096
#define GPR   (K_TOT / 16)           // 256 groups per row
#define NCTAS 148
#define NSTRIP 7                     // strips/CTA (16 N cols each)

#define K_CHUNK 64
#define NCHUNK (K_TOT / K_CHUNK)     // 64
#define THREADS 256
#define ROW_B 128                    // bytes per row: 64 halves, XOR-swizzled

#define A_BYTES (M_TOT * ROW_B)              // 32768
#define B_BYTES (NSTRIP * 16 * ROW_B)        // 14336
#define SM_A0 0
#define SM_A1 (SM_A0 + A_BYTES)
#define SM_B0 (SM_A1 + A_BYTES)
#define SM_B1 (SM_B0 + B_BYTES)
#define SMEM_BYTES (SM_B1 + B_BYTES)         // 94208

#define NB_X 1024

// ---------------- device scratch ----------------
__device__ __half g_xh[M_TOT * K_TOT]; // x in fp16 (2 MB)
__device__ int    g_norm_dtype;        // 0=fp16, 1=bf16, 2=fp32

__device__ __forceinline__ uint32_t smem_u32(const void* p) {
    uint32_t a;
    asm("{ .reg .u64 t; cvta.to.shared.u64 t, %1; cvt.u32.u64 %0, t; }" : "=r"(a) : "l"(p));
    return a;
}
#define CP_ASYNC16(dst, src) \
    asm volatile("cp.async.cg.shared.global [%0], [%1], 16;" :: "r"(dst), "l"(src) : "memory")
#define CP_COMMIT() asm volatile("cp.async.commit_group;" ::: "memory")
#define CP_WAIT0()  asm volatile("cp.async.wait_group 0;" ::: "memory")
#define LDSM_X4(r0, r1, r2, r3, a) \
    asm volatile("ldmatrix.sync.aligned.m8n8.x4.shared.b16 {%0,%1,%2,%3}, [%4];" \
        : "=r"(r0), "=r"(r1), "=r"(r2), "=r"(r3) : "r"(a))
#define MMAF32(acc, a0, a1, a2, a3, b0, b1)                                    \
    asm volatile("mma.sync.aligned.m16n8k16.row.col.f32.f16.f16.f32 "          \
        "{%0,%1,%2,%3}, {%4,%5,%6,%7}, {%8,%9}, {%0,%1,%2,%3};\n"              \
        : "+f"((acc)[0]), "+f"((acc)[1]), "+f"((acc)[2]), "+f"((acc)[3])       \
        : "r"(a0), "r"(a1), "r"(a2), "r"(a3), "r"(b0), "r"(b1))

// ---------------- prepass: x fp32->fp16 + norm dtype detect ----------------
__global__ void prepass(const uint16_t* __restrict__ pnorm,
                        const float* __restrict__ x)
{
    const int tid = threadIdx.x;
    const int b = blockIdx.x;

    if (b == 0 && tid < 32) {
        bool okh = true, okb = true, bigh = false, bigb = false;
#pragma unroll
        for (int i = 0; i < 8; i++) {
            uint16_t r = pnorm[tid * 8 + i];
            float vh = __half2float(*(const __half*)&r);
            float vb = __bfloat162float(*(const __nv_bfloat16*)&r);
            okh &= (vh > 1e-6f && vh < 1.0f);
            okb &= (vb > 1e-6f && vb < 1.0f);
            bigh |= (vh > 0.1f);
            bigb |= (vb > 0.1f);
        }
        bool allh = __all_sync(0xffffffffu, okh);
        bool allb = __all_sync(0xffffffffu, okb);
        bool anyh = __any_sync(0xffffffffu, bigh);
        bool anyb = __any_sync(0xffffffffu, bigb);
        if (tid == 0)
            g_norm_dtype = (allh && anyh) ? 0 : ((allb && anyb) ? 1 : 2);
    }

    const int base = (b * 256 + tid) * 4;
    float4 v0 = *(const float4*)(x + base);
    __half2 o[2];
    o[0] = __floats2half2_rn(v0.x, v0.y);
    o[1] = __floats2half2_rn(v0.z, v0.w);
    *(uint2*)(g_xh + base) = *(uint2*)o;
}

// dequant one group's 4 packed words into 8 half2 words; nf = norm in fp32
__device__ __forceinline__ void dequant_group(const int4 q, float nf,
                                              uint32_t hv[8])
{
    const uint32_t MAGIC = 0x64006400u;
    const __half2  magic_h2 = *(const __half2*)&MAGIC;
    __half2 tc2 = __half2half2(__float2half_rn(nf * (2.0f / 3.0f)));
    __half2 m32 = __half2half2(__float2half_rn(-nf));
    int words[4] = {q.x, q.y, q.z, q.w};
#pragma unroll
    for (int w = 0; w < 4; w++) {
        uint32_t qq = (uint32_t)words[w];
        uint32_t u01 = MAGIC | (qq & 3u) | ((qq & 0xCu) << 14);
        uint32_t u23 = MAGIC | ((qq >> 4) & 3u) | ((qq & 0xC0u) << 10);
        __half2 v01 = __hsub2(*(__half2*)&u01, magic_h2);
        __half2 v23 = __hsub2(*(__half2*)&u23, magic_h2);
        __half2 w01 = __hfma2(v01, tc2, m32);
        __half2 w23 = __hfma2(v23, tc2, m32);
        hv[w * 2]     = *(uint32_t*)&w01;
        hv[w * 2 + 1] = *(uint32_t*)&w23;
    }
}

// ---------------- main GEMM: 148 CTAs, full-M, 7 strips, staged-in-shadow ----------------
__global__ __launch_bounds__(THREADS, 1)
void l2b_hmma(const int4* __restrict__ wq,
              const uint16_t* __restrict__ pnorm,
              const __half* __restrict__ xh,
              const float* __restrict__ bias,
              float* __restrict__ out)
{
    extern __shared__ char smem[];
    const uint32_t sb = smem_u32(smem);
    const int tid  = threadIdx.x;
    const int lane = tid & 31;
    const int warp = tid >> 5;        // 0..7 : 32 M rows each, all 7 strips
    const int bid  = blockIdx.x;

    const int nbase = bid * (NSTRIP * 16);
    const int dt = g_norm_dtype;

    float acc[2][NSTRIP][2][4];
#pragma unroll
    for (int mi = 0; mi < 2; mi++)
#pragma unroll
        for (int si = 0; si < NSTRIP; si++)
#pragma unroll
            for (int e = 0; e < 2; e++)
#pragma unroll
                for (int r = 0; r < 4; r++) acc[mi][si][e][r] = 0.f;

    int4     qr[2];
    uint32_t nr[2];
    const bool has1 = (tid + 256) < NSTRIP * 64;

    auto issueA = [&](int c, uint32_t abase) {
#pragma unroll
        for (int h = 0; h < 8; h++) {
            int seg = tid + h * 256;
            int row = seg >> 3;
            int s   = seg & 7;
            const __half* src = xh + (size_t)row * K_TOT + c * K_CHUNK + s * 8;
            uint32_t dst = abase + row * ROW_B + ((s ^ (row & 7)) << 4);
            CP_ASYNC16(dst, src);
        }
        CP_COMMIT();
    };
    auto loadW = [&](int c) {
        {
            int col = nbase + (tid >> 2);
            col = col < N_TOT ? col : N_TOT - 1;
            int g   = col * GPR + c * 4 + (tid & 3);
            qr[0] = wq[g];
            if (dt == 2) nr[0] = ((const uint32_t*)pnorm)[g];
            else         nr[0] = pnorm[g];
        }
        if (has1) {
            int col = nbase + ((tid + 256) >> 2);
            col = col < N_TOT ? col : N_TOT - 1;
            int g   = col * GPR + c * 4 + (tid & 3);
            qr[1] = wq[g];
            if (dt == 2) nr[1] = ((const uint32_t*)pnorm)[g];
            else         nr[1] = pnorm[g];
        }
    };
    auto rawToF = [&](uint32_t r) -> float {
        if (dt == 0)      return __half2float(__ushort_as_half((unsigned short)r));
        else if (dt == 1) return __uint_as_float(r << 16);
        else              return __uint_as_float(r);
    };

    // STS addressing (swizzled)
    const uint32_t g0_wn = tid >> 2, g0_wgi = tid & 3;
    const uint32_t g1_wn = g0_wn + 64;
    const uint32_t sts00 = g0_wn * ROW_B + (((2 * g0_wgi) ^ (g0_wn & 7)) << 4);
    const uint32_t sts01 = g0_wn * ROW_B + (((2 * g0_wgi + 1) ^ (g0_wn & 7)) << 4);
    const uint32_t sts10 = g1_wn * ROW_B + (((2 * g0_wgi) ^ (g1_wn & 7)) << 4);
    const uint32_t sts11 = g1_wn * ROW_B + (((2 * g0_wgi + 1) ^ (g1_wn & 7)) << 4);

    auto stsB0 = [&](uint32_t bbase) {
        uint32_t hv[8];
        dequant_group(qr[0], rawToF(nr[0]), hv);
        asm volatile("st.shared.v4.b32 [%0], {%1,%2,%3,%4};"
            :: "r"(bbase + sts00), "r"(hv[0]), "r"(hv[1]), "r"(hv[2]), "r"(hv[3]) : "memory");
        asm volatile("st.shared.v4.b32 [%0], {%1,%2,%3,%4};"
            :: "r"(bbase + sts01), "r"(hv[4]), "r"(hv[5]), "r"(hv[6]), "r"(hv[7]) : "memory");
    };
    auto stsB1 = [&](uint32_t bbase) {
        if (has1) {
            uint32_t hv[8];
            dequant_group(qr[1], rawToF(nr[1]), hv);
            asm volatile("st.shared.v4.b32 [%0], {%1,%2,%3,%4};"
                :: "r"(bbase + sts10), "r"(hv[0]), "r"(hv[1]), "r"(hv[2]), "r"(hv[3]) : "memory");
            asm volatile("st.shared.v4.b32 [%0], {%1,%2,%3,%4};"
                :: "r"(bbase + sts11), "r"(hv[4]), "r"(hv[5]), "r"(hv[6]), "r"(hv[7]) : "memory");
        }
    };

    // LDSM addressing (swizzled)
    uint32_t a_rb[2], a_x7[2];
#pragma unroll
    for (int mi = 0; mi < 2; mi++) {
        int r = warp * 32 + mi * 16 + (lane & 15);
        a_rb[mi] = (uint32_t)r * ROW_B;
        a_x7[mi] = (uint32_t)(r & 7);
    }
    const uint32_t a_wb = (lane >> 4) & 1;
    const uint32_t b_nl = (uint32_t)((lane & 7) | ((lane & 16) >> 1));
    const uint32_t b_rb = b_nl * ROW_B;
    const uint32_t b_x7 = b_nl & 7;
    const uint32_t b_wb = (lane >> 3) & 1;

    // ---- prologue: stage chunk 0 fully
    issueA(0, sb + SM_A0);
    loadW(0);
    stsB0(sb + SM_B0);
    stsB1(sb + SM_B0);
    CP_WAIT0();
    __syncthreads();

    for (int c = 0; c < NCHUNK; ++c) {
        const int pb = c & 1;
        const uint32_t abase  = sb + (pb ? SM_A1 : SM_A0);
        const uint32_t bbase  = sb + (pb ? SM_B1 : SM_B0);
        const uint32_t bnext  = sb + (pb ? SM_B0 : SM_B1);
        const bool more = (c + 1 < NCHUNK);

        if (more) {
            issueA(c + 1, sb + (pb ? SM_A0 : SM_A1));
            loadW(c + 1);     // LDGs land during compute below
        }

        // ---- compute chunk c; B(c+1) staging interleaved into ks=2,3 tails
#pragma unroll
        for (int ks = 0; ks < 4; ++ks) {
            uint32_t a0, a1, a2, a3, a4, a5, a6, a7;
            {
                uint32_t w = ks * 2 + a_wb;
                LDSM_X4(a0, a1, a2, a3, abase + a_rb[0] + ((w ^ a_x7[0]) << 4));
                LDSM_X4(a4, a5, a6, a7, abase + a_rb[1] + ((w ^ a_x7[1]) << 4));
            }
#pragma unroll
            for (int si = 0; si < NSTRIP; si++) {
                uint32_t b0, b1, b2, b3;
                {
                    uint32_t w = ks * 2 + b_wb;
                    LDSM_X4(b0, b1, b2, b3,
                            bbase + (uint32_t)si * (16 * ROW_B) + b_rb + ((w ^ b_x7) << 4));
                }
#pragma unroll
                for (int e = 0; e < 2; e++) {
                    uint32_t bb0 = e ? b2 : b0;
                    uint32_t bb1 = e ? b3 : b1;
                    MMAF32(acc[0][si][e], a0, a1, a2, a3, bb0, bb1);
                    MMAF32(acc[1][si][e], a4, a5, a6, a7, bb0, bb1);
                }
            }
            if (ks == 2 && more) stsB0(bnext);
            if (ks == 3 && more) stsB1(bnext);
        }

        CP_WAIT0();        // A(c+1) arrived
        __syncthreads();   // B(c+1) STS visible
    }

    // ---- epilogue: bias + fp32 store (guarded for padded N)
#pragma unroll
    for (int mi = 0; mi < 2; mi++) {
        int r = warp * 32 + mi * 16 + (lane >> 2);
#pragma unroll
        for (int si = 0; si < NSTRIP; si++) {
#pragma unroll
            for (int e = 0; e < 2; e++) {
                int ncol = nbase + si * 16 + e * 8 + (lane & 3) * 2;
                if (ncol < N_TOT) {
                    float b0 = bias[ncol];
                    float b1 = bias[ncol + 1];
                    float2* o0 = (float2*)(out + (size_t)r * N_TOT + ncol);
                    float2* o1 = (float2*)(out + (size_t)(r + 8) * N_TOT + ncol);
                    *o0 = make_float2(acc[mi][si][e][0] + b0, acc[mi][si][e][1] + b1);
                    *o1 = make_float2(acc[mi][si][e][2] + b0, acc[mi][si][e][3] + b1);
                }
            }
        }
    }
}

// ---------------- launcher ----------------
extern "C" void kernel_launch(void* const* d_in, const int* in_sizes, int n_in,
                              void* d_out, int out_size)
{
    // Bind by size order: wq > norm > x > bias
    int order[4] = {0, 1, 2, 3};
    for (int i = 1; i < 4 && i < n_in; i++) {
        int v = order[i], j = i - 1;
        while (j >= 0 && (long long)in_sizes[order[j]] < (long long)in_sizes[v]) {
            order[j + 1] = order[j]; j--;
        }
        order[j + 1] = v;
    }
    const int4*     wq    = (const int4*)d_in[order[0]];
    const uint16_t* pnorm = (const uint16_t*)d_in[order[1]];
    const float*    x     = (const float*)d_in[order[2]];
    const float*    bias  = (const float*)d_in[order[3]];
    float* out = (float*)d_out;

    prepass<<<NB_X, 256>>>(pnorm, x);

    __half* xh_dev = nullptr;
    cudaGetSymbolAddress((void**)&xh_dev, g_xh);

    cudaFuncSetAttribute(l2b_hmma, cudaFuncAttributeMaxDynamicSharedMemorySize, SMEM_BYTES);
    l2b_hmma<<<NCTAS, THREADS, SMEM_BYTES>>>(wq, pnorm, xh_dev, bias, out);
}

// round 14
// speedup vs baseline: 1.3913x; 1.1083x over previous
#include <cuda_runtime.h>
#include <cuda_fp16.h>
#include <cuda_bf16.h>
#include <cstdint>

#define M_TOT 256
#define N_TOT 16384
#define K_TOT 4096
#define GPR   (K_TOT / 16)           // 256 groups per row
#define NCTAS 148
#define NSTRIP 7                     // strips/CTA (16 N cols each)

#define K_CHUNK 128                  // two k64 sub-tiles per chunk
#define NCHUNK (K_TOT / K_CHUNK)     // 32
#define THREADS 256
#define ROW_B 128                    // bytes per k64 sub-tile row (R12 layout)

#define ASUB (M_TOT * ROW_B)                 // 32768 per sub-tile
#define BSUB (NSTRIP * 16 * ROW_B)           // 14336 per sub-tile
#define A_BYTES (2 * ASUB)                   // 65536
#define B_BYTES (2 * BSUB)                   // 28672
#define SM_A0 0
#define SM_A1 (SM_A0 + A_BYTES)
#define SM_B0 (SM_A1 + A_BYTES)
#define SM_B1 (SM_B0 + B_BYTES)
#define SMEM_BYTES (SM_B1 + B_BYTES)         // 188416

#define NB_X 1024

// ---------------- device scratch ----------------
__device__ __half g_xh[M_TOT * K_TOT]; // x in fp16 (2 MB)
__device__ int    g_norm_dtype;        // 0=fp16, 1=bf16, 2=fp32

__device__ __forceinline__ uint32_t smem_u32(const void* p) {
    uint32_t a;
    asm("{ .reg .u64 t; cvta.to.shared.u64 t, %1; cvt.u32.u64 %0, t; }" : "=r"(a) : "l"(p));
    return a;
}
#define CP_ASYNC16(dst, src) \
    asm volatile("cp.async.cg.shared.global [%0], [%1], 16;" :: "r"(dst), "l"(src) : "memory")
#define CP_COMMIT() asm volatile("cp.async.commit_group;" ::: "memory")
#define CP_WAIT0()  asm volatile("cp.async.wait_group 0;" ::: "memory")
#define LDSM_X4(r0, r1, r2, r3, a) \
    asm volatile("ldmatrix.sync.aligned.m8n8.x4.shared.b16 {%0,%1,%2,%3}, [%4];" \
        : "=r"(r0), "=r"(r1), "=r"(r2), "=r"(r3) : "r"(a))
#define MMAF32(acc, a0, a1, a2, a3, b0, b1)                                    \
    asm volatile("mma.sync.aligned.m16n8k16.row.col.f32.f16.f16.f32 "          \
        "{%0,%1,%2,%3}, {%4,%5,%6,%7}, {%8,%9}, {%0,%1,%2,%3};\n"              \
        : "+f"((acc)[0]), "+f"((acc)[1]), "+f"((acc)[2]), "+f"((acc)[3])       \
        : "r"(a0), "r"(a1), "r"(a2), "r"(a3), "r"(b0), "r"(b1))

// ---------------- prepass: x fp32->fp16 + norm dtype detect ----------------
__global__ void prepass(const uint16_t* __restrict__ pnorm,
                        const float* __restrict__ x)
{
    const int tid = threadIdx.x;
    const int b = blockIdx.x;

    if (b == 0 && tid < 32) {
        bool okh = true, okb = true, bigh = false, bigb = false;
#pragma unroll
        for (int i = 0; i < 8; i++) {
            uint16_t r = pnorm[tid * 8 + i];
            float vh = __half2float(*(const __half*)&r);
            float vb = __bfloat162float(*(const __nv_bfloat16*)&r);
            okh &= (vh > 1e-6f && vh < 1.0f);
            okb &= (vb > 1e-6f && vb < 1.0f);
            bigh |= (vh > 0.1f);
            bigb |= (vb > 0.1f);
        }
        bool allh = __all_sync(0xffffffffu, okh);
        bool allb = __all_sync(0xffffffffu, okb);
        bool anyh = __any_sync(0xffffffffu, bigh);
        bool anyb = __any_sync(0xffffffffu, bigb);
        if (tid == 0)
            g_norm_dtype = (allh && anyh) ? 0 : ((allb && anyb) ? 1 : 2);
    }

    const int base = (b * 256 + tid) * 4;
    float4 v0 = *(const float4*)(x + base);
    __half2 o[2];
    o[0] = __floats2half2_rn(v0.x, v0.y);
    o[1] = __floats2half2_rn(v0.z, v0.w);
    *(uint2*)(g_xh + base) = *(uint2*)o;
}

// dequant one group's 4 packed words into 8 half2 words; nf = norm in fp32
__device__ __forceinline__ void dequant_group(const int4 q, float nf,
                                              uint32_t hv[8])
{
    const uint32_t MAGIC = 0x64006400u;
    const __half2  magic_h2 = *(const __half2*)&MAGIC;
    __half2 tc2 = __half2half2(__float2half_rn(nf * (2.0f / 3.0f)));
    __half2 m32 = __half2half2(__float2half_rn(-nf));
    int words[4] = {q.x, q.y, q.z, q.w};
#pragma unroll
    for (int w = 0; w < 4; w++) {
        uint32_t qq = (uint32_t)words[w];
        uint32_t u01 = MAGIC | (qq & 3u) | ((qq & 0xCu) << 14);
        uint32_t u23 = MAGIC | ((qq >> 4) & 3u) | ((qq & 0xC0u) << 10);
        __half2 v01 = __hsub2(*(__half2*)&u01, magic_h2);
        __half2 v23 = __hsub2(*(__half2*)&u23, magic_h2);
        __half2 w01 = __hfma2(v01, tc2, m32);
        __half2 w23 = __hfma2(v23, tc2, m32);
        hv[w * 2]     = *(uint32_t*)&w01;
        hv[w * 2 + 1] = *(uint32_t*)&w23;
    }
}

// ---------------- main GEMM: 148 CTAs, full-M, 7 strips, K_CHUNK=128 ----------------
__global__ __launch_bounds__(THREADS, 1)
void l2b_hmma(const int4* __restrict__ wq,
              const uint16_t* __restrict__ pnorm,
              const __half* __restrict__ xh,
              const float* __restrict__ bias,
              float* __restrict__ out)
{
    extern __shared__ char smem[];
    const uint32_t sb = smem_u32(smem);
    const int tid  = threadIdx.x;
    const int lane = tid & 31;
    const int warp = tid >> 5;        // 0..7 : 32 M rows each, all 7 strips
    const int bid  = blockIdx.x;

    const int nbase = bid * (NSTRIP * 16);
    const int dt = g_norm_dtype;

    float acc[2][NSTRIP][2][4];
#pragma unroll
    for (int mi = 0; mi < 2; mi++)
#pragma unroll
        for (int si = 0; si < NSTRIP; si++)
#pragma unroll
            for (int e = 0; e < 2; e++)
#pragma unroll
                for (int r = 0; r < 4; r++) acc[mi][si][e][r] = 0.f;

    int4     qr[2];
    uint32_t nr[2];
    const bool has1 = (tid + 256) < NSTRIP * 64;

    // A staging: per chunk, 4096 16B segs = 2 subs x (256 rows x 8 segs)
    auto issueA = [&](int c, uint32_t abase) {
#pragma unroll
        for (int h = 0; h < 16; h++) {
            int sub = h >> 3;
            int seg = tid + (h & 7) * 256;
            int row = seg >> 3;
            int s   = seg & 7;
            const __half* src = xh + (size_t)row * K_TOT + c * K_CHUNK + sub * 64 + s * 8;
            uint32_t dst = abase + sub * ASUB + row * ROW_B + ((s ^ (row & 7)) << 4);
            CP_ASYNC16(dst, src);
        }
        CP_COMMIT();
    };
    // B weight load for (chunk c, sub-tile s): k64 index = 2c + s
    auto loadW = [&](int c, int s) {
        int k64 = c * 2 + s;
        {
            int col = nbase + (tid >> 2);
            col = col < N_TOT ? col : N_TOT - 1;
            int g   = col * GPR + k64 * 4 + (tid & 3);
            qr[0] = wq[g];
            if (dt == 2) nr[0] = ((const uint32_t*)pnorm)[g];
            else         nr[0] = pnorm[g];
        }
        if (has1) {
            int col = nbase + ((tid + 256) >> 2);
            col = col < N_TOT ? col : N_TOT - 1;
            int g   = col * GPR + k64 * 4 + (tid & 3);
            qr[1] = wq[g];
            if (dt == 2) nr[1] = ((const uint32_t*)pnorm)[g];
            else         nr[1] = pnorm[g];
        }
    };
    auto rawToF = [&](uint32_t r) -> float {
        if (dt == 0)      return __half2float(__ushort_as_half((unsigned short)r));
        else if (dt == 1) return __uint_as_float(r << 16);
        else              return __uint_as_float(r);
    };

    // STS addressing (R12 swizzle, per sub-tile)
    const uint32_t g0_wn = tid >> 2, g0_wgi = tid & 3;
    const uint32_t g1_wn = g0_wn + 64;
    const uint32_t sts00 = g0_wn * ROW_B + (((2 * g0_wgi) ^ (g0_wn & 7)) << 4);
    const uint32_t sts01 = g0_wn * ROW_B + (((2 * g0_wgi + 1) ^ (g0_wn & 7)) << 4);
    const uint32_t sts10 = g1_wn * ROW_B + (((2 * g0_wgi) ^ (g1_wn & 7)) << 4);
    const uint32_t sts11 = g1_wn * ROW_B + (((2 * g0_wgi + 1) ^ (g1_wn & 7)) << 4);

    auto stsB0 = [&](uint32_t bsubbase) {
        uint32_t hv[8];
        dequant_group(qr[0], rawToF(nr[0]), hv);
        asm volatile("st.shared.v4.b32 [%0], {%1,%2,%3,%4};"
            :: "r"(bsubbase + sts00), "r"(hv[0]), "r"(hv[1]), "r"(hv[2]), "r"(hv[3]) : "memory");
        asm volatile("st.shared.v4.b32 [%0], {%1,%2,%3,%4};"
            :: "r"(bsubbase + sts01), "r"(hv[4]), "r"(hv[5]), "r"(hv[6]), "r"(hv[7]) : "memory");
    };
    auto stsB1 = [&](uint32_t bsubbase) {
        if (has1) {
            uint32_t hv[8];
            dequant_group(qr[1], rawToF(nr[1]), hv);
            asm volatile("st.shared.v4.b32 [%0], {%1,%2,%3,%4};"
                :: "r"(bsubbase + sts10), "r"(hv[0]), "r"(hv[1]), "r"(hv[2]), "r"(hv[3]) : "memory");
            asm volatile("st.shared.v4.b32 [%0], {%1,%2,%3,%4};"
                :: "r"(bsubbase + sts11), "r"(hv[4]), "r"(hv[5]), "r"(hv[6]), "r"(hv[7]) : "memory");
        }
    };

    // LDSM addressing (R12 swizzle, per sub-tile)
    uint32_t a_rb[2], a_x7[2];
#pragma unroll
    for (int mi = 0; mi < 2; mi++) {
        int r = warp * 32 + mi * 16 + (lane & 15);
        a_rb[mi] = (uint32_t)r * ROW_B;
        a_x7[mi] = (uint32_t)(r & 7);
    }
    const uint32_t a_wb = (lane >> 4) & 1;
    const uint32_t b_nl = (uint32_t)((lane & 7) | ((lane & 16) >> 1));
    const uint32_t b_rb = b_nl * ROW_B;
    const uint32_t b_x7 = b_nl & 7;
    const uint32_t b_wb = (lane >> 3) & 1;

    // ---- prologue: stage chunk 0 fully
    issueA(0, sb + SM_A0);
    loadW(0, 0);
    stsB0(sb + SM_B0);
    stsB1(sb + SM_B0);
    loadW(0, 1);
    stsB0(sb + SM_B0 + BSUB);
    stsB1(sb + SM_B0 + BSUB);
    CP_WAIT0();
    __syncthreads();

    for (int c = 0; c < NCHUNK; ++c) {
        const int pb = c & 1;
        const uint32_t abase  = sb + (pb ? SM_A1 : SM_A0);
        const uint32_t bbase  = sb + (pb ? SM_B1 : SM_B0);
        const uint32_t bnext  = sb + (pb ? SM_B0 : SM_B1);
        const bool more = (c + 1 < NCHUNK);

        if (more) {
            issueA(c + 1, sb + (pb ? SM_A0 : SM_A1));
            loadW(c + 1, 0);   // sub0 weights land during ks 0-1
        }

        // ---- compute chunk c: 8 k-steps over 2 sub-tiles; B(c+1) staged in shadow
#pragma unroll
        for (int ks = 0; ks < 8; ++ks) {
            const uint32_t asub = abase + (ks >> 2) * ASUB;
            const uint32_t bsub = bbase + (ks >> 2) * BSUB;
            const uint32_t ksl = ks & 3;
            uint32_t a0, a1, a2, a3, a4, a5, a6, a7;
            {
                uint32_t w = ksl * 2 + a_wb;
                LDSM_X4(a0, a1, a2, a3, asub + a_rb[0] + ((w ^ a_x7[0]) << 4));
                LDSM_X4(a4, a5, a6, a7, asub + a_rb[1] + ((w ^ a_x7[1]) << 4));
            }
#pragma unroll
            for (int si = 0; si < NSTRIP; si++) {
                uint32_t b0, b1, b2, b3;
                {
                    uint32_t w = ksl * 2 + b_wb;
                    LDSM_X4(b0, b1, b2, b3,
                            bsub + (uint32_t)si * (16 * ROW_B) + b_rb + ((w ^ b_x7) << 4));
                }
#pragma unroll
                for (int e = 0; e < 2; e++) {
                    uint32_t bb0 = e ? b2 : b0;
                    uint32_t bb1 = e ? b3 : b1;
                    MMAF32(acc[0][si][e], a0, a1, a2, a3, bb0, bb1);
                    MMAF32(acc[1][si][e], a4, a5, a6, a7, bb0, bb1);
                }
            }
            if (more) {
                if (ks == 2) stsB0(bnext);
                if (ks == 3) { stsB1(bnext); loadW(c + 1, 1); }
                if (ks == 5) stsB0(bnext + BSUB);
                if (ks == 6) stsB1(bnext + BSUB);
            }
        }

        CP_WAIT0();        // A(c+1) arrived
        __syncthreads();   // B(c+1) STS visible
    }

    // ---- epilogue: bias + fp32 store (guarded for padded N)
#pragma unroll
    for (int mi = 0; mi < 2; mi++) {
        int r = warp * 32 + mi * 16 + (lane >> 2);
#pragma unroll
        for (int si = 0; si < NSTRIP; si++) {
#pragma unroll
            for (int e = 0; e < 2; e++) {
                int ncol = nbase + si * 16 + e * 8 + (lane & 3) * 2;
                if (ncol < N_TOT) {
                    float b0 = bias[ncol];
                    float b1 = bias[ncol + 1];
                    float2* o0 = (float2*)(out + (size_t)r * N_TOT + ncol);
                    float2* o1 = (float2*)(out + (size_t)(r + 8) * N_TOT + ncol);
                    *o0 = make_float2(acc[mi][si][e][0] + b0, acc[mi][si][e][1] + b1);
                    *o1 = make_float2(acc[mi][si][e][2] + b0, acc[mi][si][e][3] + b1);
                }
            }
        }
    }
}

// ---------------- launcher ----------------
extern "C" void kernel_launch(void* const* d_in, const int* in_sizes, int n_in,
                              void* d_out, int out_size)
{
    // Bind by size order: wq > norm > x > bias
    int order[4] = {0, 1, 2, 3};
    for (int i = 1; i < 4 && i < n_in; i++) {
        int v = order[i], j = i - 1;
        while (j >= 0 && (long long)in_sizes[order[j]] < (long long)in_sizes[v]) {
            order[j + 1] = order[j]; j--;
        }
        order[j + 1] = v;
    }
    const int4*     wq    = (const int4*)d_in[order[0]];
    const uint16_t* pnorm = (const uint16_t*)d_in[order[1]];
    const float*    x     = (const float*)d_in[order[2]];
    const float*    bias  = (const float*)d_in[order[3]];
    float* out = (float*)d_out;

    prepass<<<NB_X, 256>>>(pnorm, x);

    __half* xh_dev = nullptr;
    cudaGetSymbolAddress((void**)&xh_dev, g_xh);

    cudaFuncSetAttribute(l2b_hmma, cudaFuncAttributeMaxDynamicSharedMemorySize, SMEM_BYTES);
    l2b_hmma<<<NCTAS, THREADS, SMEM_BYTES>>>(wq, pnorm, xh_dev, bias, out);
}